// round 7
// baseline (speedup 1.0000x reference)
#include <cuda_runtime.h>
#include <cuda_bf16.h>
#include <stdint.h>
#include <math.h>

// ---------------- problem constants ----------------
#define S_ 2048
#define D_ 2048
#define H_ 16
#define QR_ 1536
#define KVR_ 512
#define NOPE_ 128
#define RD_ 64
#define VD_ 128
#define QKD_ 192          // NOPE + RD
#define DFF_ 8192
#define HQKD_ (H_*QKD_)   // 3072
#define HKV_ (H_*(NOPE_+VD_)) // 4096

// ---------------- scratch (static device globals; allocation-free) ----------------
__device__ float g_hs [(size_t)S_*D_];
__device__ float g_qa [(size_t)S_*QR_];
__device__ float g_q  [(size_t)S_*HQKD_];
__device__ float g_kva[(size_t)S_*(KVR_+RD_)];
__device__ float g_ckv[(size_t)S_*KVR_];
__device__ float g_kv [(size_t)S_*HKV_];
__device__ float g_kpe[(size_t)S_*RD_];
__device__ float g_kf [(size_t)H_*S_*QKD_];
__device__ float g_sc [(size_t)H_*S_*S_];   // 256 MB
__device__ float g_ao [(size_t)S_*D_];
__device__ float g_x2 [(size_t)S_*D_];
__device__ float g_h2 [(size_t)S_*D_];
__device__ float g_ffn[(size_t)S_*DFF_];

// ---------------- tf32 helpers ----------------
__device__ __forceinline__ uint32_t f2tf(float f) {
    uint32_t r;
    asm("cvt.rna.tf32.f32 %0, %1;" : "=r"(r) : "f"(f));
    return r;
}

__device__ __forceinline__ void mma_tf32(float* c, const uint32_t* a, const uint32_t* b) {
    asm volatile(
        "mma.sync.aligned.m16n8k8.row.col.f32.tf32.tf32.f32 "
        "{%0,%1,%2,%3}, {%4,%5,%6,%7}, {%8,%9}, {%0,%1,%2,%3};"
        : "+f"(c[0]), "+f"(c[1]), "+f"(c[2]), "+f"(c[3])
        : "r"(a[0]), "r"(a[1]), "r"(a[2]), "r"(a[3]),
          "r"(b[0]), "r"(b[1]));
}

// ---------------- tensor-core GEMM (fragment-major smem) ----------------
// C[M,N] = A[M,K] @ op(B); A row-major (lda).
//   BT=false: B is [K,N] (ldb row stride)
//   BT=true : B is [N,K] (ldb row stride)  => C = A @ B^T
// EPI bitmask: 1=causal mask+scale, 2=+bias[n], 4=gelu(exact), 8=+aux[m,n],
//              16=causal K-limit (K_eff = m0+BM)
// Requirements: M % 128 == 0, K % 16 == 0, N % 4 == 0 (all calls satisfy).
#define BM 128
#define BN 128
#define BKT 16

// Fragment layouts (tf32 m16n8k8):
//   A value (m,k): reg = ((k&4)?2:0) | ((m>>3)&1); lane = (m&7)*4 + (k&3);
//                  mblk = m>>4; ks = k>>3.
//   B value (n,k): reg = (k&4)?1:0;  lane = (n&7)*4 + (k&3);
//                  nblk = n>>3; ks = k>>3.
// Reader (lane L): A row-in-16 = L>>2, k-in-4 = L&3 -> one LDS.128 per (ks,mblk);
//                  B col-in-8 = L>>2, k-in-4 = L&3 -> one LDS.64 per (ks,nblk).

template<bool BT, int EPI>
__global__ void __launch_bounds__(256) tcgemm_k(
    const float* __restrict__ A, int lda, long long sA,
    const float* __restrict__ B, int ldb, long long sB,
    float* __restrict__ C, int ldc, long long sC,
    int M, int N, int K, float scale,
    const float* __restrict__ bias,
    const float* __restrict__ aux, int ldaux, long long sAux)
{
    const int bz = blockIdx.z;
    const float* Ab = A + (long long)bz * sA;
    const float* Bb = B + (long long)bz * sB;
    float* Cb = C + (long long)bz * sC;
    const float* auxb = aux ? aux + (long long)bz * sAux : nullptr;

    const int m0 = blockIdx.y * BM;
    const int n0 = blockIdx.x * BN;
    if ((EPI & 1) && n0 > m0 + BM - 1) return;   // fully-masked causal block

    int Keff = K;
    if (EPI & 16) { int kl = m0 + BM; Keff = kl < K ? kl : K; }

    __shared__ uint32_t Asf[2][2][8][32][4];    // [buf][ks][mblk][lane][reg]
    __shared__ uint32_t Bsf[2][2][16][32][2];   // [buf][ks][nblk][lane][reg]

    const int tid = threadIdx.x;
    const int lane = tid & 31;
    const int wid = tid >> 5;
    const int mb0 = (wid & 1) * 4;    // warp mblk base (wm = mb0*16)
    const int nb0 = (wid >> 1) * 4;   // warp nblk base (wn = nb0*8)

    float acc[4][4][4];
    #pragma unroll
    for (int i = 0; i < 4; i++)
        #pragma unroll
        for (int j = 0; j < 4; j++)
            #pragma unroll
            for (int c = 0; c < 4; c++) acc[i][j][c] = 0.f;

    // global-load staging (same coverage as proven R4 kernel)
    float4 ag0, ag1, bg0, bg1;
    const int ar = tid >> 2;           // A row within tile (0..63), +64 for second
    const int ak = (tid & 3) * 4;      // A k-offset (0,4,8,12)
    const int bk_f = tid >> 5;         // BT=false: k row (0..7), +8
    const int bn_f = (tid & 31) * 4;   // BT=false: n offset (multiple of 4; %8 in {0,4})
    const int bn_t = tid >> 2;         // BT=true : n row (0..63), +64
    const int bk_t = (tid & 3) * 4;    // BT=true : k offset

    const float4 z4 = make_float4(0.f, 0.f, 0.f, 0.f);

    auto ldg = [&](int k0) {
        ag0 = *(const float4*)(Ab + (size_t)(m0 + ar) * lda + k0 + ak);
        ag1 = *(const float4*)(Ab + (size_t)(m0 + ar + 64) * lda + k0 + ak);
        if (!BT) {
            int n = n0 + bn_f;
            bool ok = n < N;
            bg0 = ok ? *(const float4*)(Bb + (size_t)(k0 + bk_f) * ldb + n) : z4;
            bg1 = ok ? *(const float4*)(Bb + (size_t)(k0 + bk_f + 8) * ldb + n) : z4;
        } else {
            int n1 = n0 + bn_t, n2 = n1 + 64;
            bg0 = (n1 < N) ? *(const float4*)(Bb + (size_t)n1 * ldb + k0 + bk_t) : z4;
            bg1 = (n2 < N) ? *(const float4*)(Bb + (size_t)n2 * ldb + k0 + bk_t) : z4;
        }
    };

    // A store: fixed row m (tile-local), k = kq..kq+3 (kq multiple of 4)
    auto stA = [&](int buf, int m, int kq, const float4& v) {
        int ks = kq >> 3;
        int reg = ((kq & 4) ? 2 : 0) | ((m >> 3) & 1);
        uint32_t* p = &Asf[buf][ks][(m >> 4)][0][0];
        int lb = (m & 7) * 4;
        p[(lb + 0) * 4 + reg] = f2tf(v.x);
        p[(lb + 1) * 4 + reg] = f2tf(v.y);
        p[(lb + 2) * 4 + reg] = f2tf(v.z);
        p[(lb + 3) * 4 + reg] = f2tf(v.w);
    };
    // B store (BT=true): fixed col n, k = kq..kq+3
    auto stB_k4 = [&](int buf, int n, int kq, const float4& v) {
        int ks = kq >> 3;
        int reg = (kq & 4) ? 1 : 0;
        uint32_t* p = &Bsf[buf][ks][(n >> 3)][0][0];
        int lb = (n & 7) * 4;
        p[(lb + 0) * 2 + reg] = f2tf(v.x);
        p[(lb + 1) * 2 + reg] = f2tf(v.y);
        p[(lb + 2) * 2 + reg] = f2tf(v.z);
        p[(lb + 3) * 2 + reg] = f2tf(v.w);
    };
    // B store (BT=false): fixed k, n = nq..nq+3 (nq%8 in {0,4} -> same nblk)
    auto stB_n4 = [&](int buf, int nq, int k, const float4& v) {
        int ks = k >> 3;
        int k8 = k & 7;
        int reg = (k8 >= 4) ? 1 : 0;
        int k3 = k8 & 3;
        uint32_t* p = &Bsf[buf][ks][(nq >> 3)][0][0];
        int nb = nq & 7;
        p[((nb + 0) * 4 + k3) * 2 + reg] = f2tf(v.x);
        p[((nb + 1) * 4 + k3) * 2 + reg] = f2tf(v.y);
        p[((nb + 2) * 4 + k3) * 2 + reg] = f2tf(v.z);
        p[((nb + 3) * 4 + k3) * 2 + reg] = f2tf(v.w);
    };

    auto sts = [&](int buf) {
        stA(buf, ar, ak, ag0);
        stA(buf, ar + 64, ak, ag1);
        if (!BT) {
            stB_n4(buf, bn_f, bk_f, bg0);
            stB_n4(buf, bn_f, bk_f + 8, bg1);
        } else {
            stB_k4(buf, bn_t, bk_t, bg0);
            stB_k4(buf, bn_t + 64, bk_t, bg1);
        }
    };

    auto comp = [&](int buf) {
        #pragma unroll
        for (int ks = 0; ks < 2; ks++) {
            uint4 a4[4];
            uint2 b2[4];
            #pragma unroll
            for (int mt = 0; mt < 4; mt++)
                a4[mt] = *(const uint4*)&Asf[buf][ks][mb0 + mt][lane][0];
            #pragma unroll
            for (int nt = 0; nt < 4; nt++)
                b2[nt] = *(const uint2*)&Bsf[buf][ks][nb0 + nt][lane][0];
            #pragma unroll
            for (int mt = 0; mt < 4; mt++)
                #pragma unroll
                for (int nt = 0; nt < 4; nt++)
                    mma_tf32(acc[mt][nt], (const uint32_t*)&a4[mt],
                             (const uint32_t*)&b2[nt]);
        }
    };

    const int T = Keff / BKT;
    ldg(0);
    sts(0);
    __syncthreads();
    for (int t = 0; t < T; t++) {
        int buf = t & 1;
        if (t + 1 < T) ldg((t + 1) * BKT);
        comp(buf);
        if (t + 1 < T) sts(buf ^ 1);
        __syncthreads();
    }

    // epilogue (C fragment: c0,c1 at row lane>>2, cols 2*(lane&3); c2,c3 row+8)
    #pragma unroll
    for (int mt = 0; mt < 4; mt++) {
        int gm0 = m0 + mb0 * 16 + mt * 16 + (lane >> 2);
        #pragma unroll
        for (int nt = 0; nt < 4; nt++) {
            int gn = n0 + nb0 * 8 + nt * 8 + 2 * (lane & 3);
            if (gn >= N) continue;
            #pragma unroll
            for (int h = 0; h < 2; h++) {
                int gm = gm0 + h * 8;
                float v0 = acc[mt][nt][h * 2 + 0];
                float v1 = acc[mt][nt][h * 2 + 1];
                if (EPI & 1) {
                    v0 = (gn     <= gm) ? v0 * scale : -1e30f;
                    v1 = (gn + 1 <= gm) ? v1 * scale : -1e30f;
                }
                if (EPI & 2) { v0 += bias[gn]; v1 += bias[gn + 1]; }
                if (EPI & 4) {
                    v0 = 0.5f * v0 * (1.f + erff(v0 * 0.70710678118654752f));
                    v1 = 0.5f * v1 * (1.f + erff(v1 * 0.70710678118654752f));
                }
                if (EPI & 8) {
                    v0 += auxb[(long long)gm * ldaux + gn];
                    v1 += auxb[(long long)gm * ldaux + gn + 1];
                }
                *(float2*)&Cb[(long long)gm * ldc + gn] = make_float2(v0, v1);
            }
        }
    }
}

// ---------------- rmsnorm: one block per row ----------------
__global__ void rmsnorm_k(const float* __restrict__ src, int sld,
                          float* __restrict__ dst, int dld,
                          const float* __restrict__ w, int n)
{
    __shared__ float sh[8];
    __shared__ float rs_sh;
    long long r = blockIdx.x;
    const float* s = src + r * sld;
    float* d = dst + r * dld;
    int tid = threadIdx.x;

    float ss = 0.f;
    for (int i = tid; i < n; i += 256) { float v = s[i]; ss += v * v; }
    #pragma unroll
    for (int o = 16; o; o >>= 1) ss += __shfl_xor_sync(0xffffffffu, ss, o);
    if ((tid & 31) == 0) sh[tid >> 5] = ss;
    __syncthreads();
    if (tid == 0) {
        float t = 0.f;
        #pragma unroll
        for (int i = 0; i < 8; i++) t += sh[i];
        rs_sh = rsqrtf(t / (float)n + 1e-5f);
    }
    __syncthreads();
    float rs = rs_sh;
    for (int i = tid; i < n; i += 256) d[i] = s[i] * rs * w[i];
}

// ---------------- RoPE ----------------
__device__ __forceinline__ void rope_pair(int s, int j, float x0, float x1,
                                          float& o_lo, float& o_hi)
{
    float e = (float)(2 * j) / 64.f;
    float inv = 1.f / powf(10000.f, e);
    float ang = (float)s * inv;
    float sn, c;
    sincosf(ang, &sn, &c);
    o_lo = x0 * c - x1 * sn;
    o_hi = x1 * c + x0 * sn;
}

__global__ void rope_q_k(float* __restrict__ q)   // in-place on pe slice of g_q
{
    int s = blockIdx.x, h = blockIdx.y, j = threadIdx.x;  // 32 threads
    float* p = q + (long long)s * HQKD_ + h * QKD_ + NOPE_;
    float x0 = p[2 * j], x1 = p[2 * j + 1];
    __syncwarp();
    float lo, hi;
    rope_pair(s, j, x0, x1, lo, hi);
    p[j] = lo;
    p[32 + j] = hi;
}

__global__ void rope_kpe_k(const float* __restrict__ kva, float* __restrict__ kpe)
{
    int s = blockIdx.x, j = threadIdx.x;
    const float* p = kva + (long long)s * (KVR_ + RD_) + KVR_;
    float lo, hi;
    rope_pair(s, j, p[2 * j], p[2 * j + 1], lo, hi);
    kpe[(long long)s * RD_ + j] = lo;
    kpe[(long long)s * RD_ + 32 + j] = hi;
}

// ---------------- pack k_full = [k_nope | roped k_pe] per head ----------------
__global__ void pack_kf_k(const float* __restrict__ kv,
                          const float* __restrict__ kpe,
                          float* __restrict__ kf)
{
    int s = blockIdx.x, h = blockIdx.y, c = threadIdx.x;  // 192 threads
    float v = (c < NOPE_) ? kv[(long long)s * HKV_ + h * (NOPE_ + VD_) + c]
                          : kpe[(long long)s * RD_ + (c - NOPE_)];
    kf[((long long)h * S_ + s) * QKD_ + c] = v;
}

// ---------------- causal softmax (zero tail only up to 128-block boundary) ----
__global__ void softmax_k(float* __restrict__ sc)
{
    __shared__ float sh[8];
    __shared__ float bval;
    int q = blockIdx.x, h = blockIdx.y;
    float* row = sc + ((long long)h * S_ + q) * (long long)S_;
    int n = q + 1;
    int tid = threadIdx.x;

    float mx = -1e30f;
    for (int i = tid; i < n; i += 256) mx = fmaxf(mx, row[i]);
    #pragma unroll
    for (int o = 16; o; o >>= 1) mx = fmaxf(mx, __shfl_xor_sync(0xffffffffu, mx, o));
    if ((tid & 31) == 0) sh[tid >> 5] = mx;
    __syncthreads();
    if (tid == 0) {
        float m = sh[0];
        #pragma unroll
        for (int i = 1; i < 8; i++) m = fmaxf(m, sh[i]);
        bval = m;
    }
    __syncthreads();
    float M = bval;
    __syncthreads();

    float sum = 0.f;
    for (int i = tid; i < n; i += 256) {
        float e = expf(row[i] - M);
        row[i] = e;
        sum += e;
    }
    #pragma unroll
    for (int o = 16; o; o >>= 1) sum += __shfl_xor_sync(0xffffffffu, sum, o);
    if ((tid & 31) == 0) sh[tid >> 5] = sum;
    __syncthreads();
    if (tid == 0) {
        float t = 0.f;
        #pragma unroll
        for (int i = 0; i < 8; i++) t += sh[i];
        bval = 1.f / t;
    }
    __syncthreads();
    float inv = bval;
    for (int i = tid; i < n; i += 256) row[i] *= inv;
    // PV GEMM only reads K up to this row's 128-block end — zero just that tail.
    int zend = ((q >> 7) + 1) << 7;
    for (int i = n + tid; i < zend; i += 256) row[i] = 0.f;
}

// ---------------- host side ----------------
struct Bufs {
    float *hs, *qa, *q, *kva, *ckv, *kv, *kpe, *kf, *sc, *ao, *x2, *h2, *ffn;
};

static Bufs get_bufs()
{
    static Bufs b = [] {
        Bufs t;
        cudaGetSymbolAddress((void**)&t.hs,  g_hs);
        cudaGetSymbolAddress((void**)&t.qa,  g_qa);
        cudaGetSymbolAddress((void**)&t.q,   g_q);
        cudaGetSymbolAddress((void**)&t.kva, g_kva);
        cudaGetSymbolAddress((void**)&t.ckv, g_ckv);
        cudaGetSymbolAddress((void**)&t.kv,  g_kv);
        cudaGetSymbolAddress((void**)&t.kpe, g_kpe);
        cudaGetSymbolAddress((void**)&t.kf,  g_kf);
        cudaGetSymbolAddress((void**)&t.sc,  g_sc);
        cudaGetSymbolAddress((void**)&t.ao,  g_ao);
        cudaGetSymbolAddress((void**)&t.x2,  g_x2);
        cudaGetSymbolAddress((void**)&t.h2,  g_h2);
        cudaGetSymbolAddress((void**)&t.ffn, g_ffn);
        return t;
    }();
    return b;
}

template<bool BT, int EPI>
static void gemm(const float* A, int lda, long long sA,
                 const float* B, int ldb, long long sB,
                 float* C, int ldc, long long sC,
                 int M, int N, int K, int batch,
                 float scale = 1.f,
                 const float* bias = nullptr,
                 const float* aux = nullptr, int ldaux = 0, long long sAux = 0)
{
    dim3 grid((N + BN - 1) / BN, (M + BM - 1) / BM, batch);
    tcgemm_k<BT, EPI><<<grid, 256>>>(A, lda, sA, B, ldb, sB, C, ldc, sC,
                                     M, N, K, scale, bias, aux, ldaux, sAux);
}

extern "C" void kernel_launch(void* const* d_in, const int* in_sizes, int n_in,
                              void* d_out, int out_size)
{
    const float* x        = (const float*)d_in[0];
    const float* norm1_w  = (const float*)d_in[1];
    const float* q_a_w    = (const float*)d_in[2];
    const float* q_a_ln_w = (const float*)d_in[3];
    const float* q_b_w    = (const float*)d_in[4];
    const float* kv_a_w   = (const float*)d_in[5];
    const float* kv_a_ln_w= (const float*)d_in[6];
    const float* kv_b_w   = (const float*)d_in[7];
    const float* o_w      = (const float*)d_in[8];
    const float* norm2_w  = (const float*)d_in[9];
    const float* ffn_w1   = (const float*)d_in[10];
    const float* ffn_b1   = (const float*)d_in[11];
    const float* ffn_w2   = (const float*)d_in[12];
    const float* ffn_b2   = (const float*)d_in[13];
    float* out = (float*)d_out;

    Bufs b = get_bufs();

    // 1. hs = rmsnorm(x) * norm1_w   (B=1 so layout is (S, D))
    rmsnorm_k<<<S_, 256>>>(x, D_, b.hs, D_, norm1_w, D_);

    // 2. q_a = hs @ q_a_w ; rmsnorm ; q = @ q_b_w
    gemm<false, 0>(b.hs, D_, 0, q_a_w, QR_, 0, b.qa, QR_, 0, S_, QR_, D_, 1);
    rmsnorm_k<<<S_, 256>>>(b.qa, QR_, b.qa, QR_, q_a_ln_w, QR_);
    gemm<false, 0>(b.qa, QR_, 0, q_b_w, HQKD_, 0, b.q, HQKD_, 0, S_, HQKD_, QR_, 1);

    // 3. kv_a = hs @ kv_a_w ; split ; rmsnorm ; kv = @ kv_b_w
    gemm<false, 0>(b.hs, D_, 0, kv_a_w, KVR_ + RD_, 0, b.kva, KVR_ + RD_, 0,
                   S_, KVR_ + RD_, D_, 1);
    rmsnorm_k<<<S_, 256>>>(b.kva, KVR_ + RD_, b.ckv, KVR_, kv_a_ln_w, KVR_);
    gemm<false, 0>(b.ckv, KVR_, 0, kv_b_w, HKV_, 0, b.kv, HKV_, 0, S_, HKV_, KVR_, 1);

    // 4. RoPE + pack k_full
    rope_q_k<<<dim3(S_, H_), 32>>>(b.q);
    rope_kpe_k<<<S_, 32>>>(b.kva, b.kpe);
    pack_kf_k<<<dim3(S_, H_), 192>>>(b.kv, b.kpe, b.kf);

    // 5. scores = (q_full @ k_full^T) * 1/sqrt(192), causal (upper blocks skipped)
    const float scale = 0.072168783648703216f; // 1/sqrt(192)
    gemm<true, 1>(b.q, HQKD_, (long long)QKD_,
                  b.kf, QKD_, (long long)S_ * QKD_,
                  b.sc, S_, (long long)S_ * S_,
                  S_, S_, QKD_, H_, scale);

    // 6. causal softmax (zeros tail to the 128-block boundary)
    softmax_k<<<dim3(S_, H_), 256>>>(b.sc);

    // 7. attn_out = P @ V  (V strided in kv; causal K-limit: K_eff = m0+128)
    gemm<false, 16>(b.sc, S_, (long long)S_ * S_,
                    b.kv + NOPE_, HKV_, (long long)(NOPE_ + VD_),
                    b.ao, D_, (long long)VD_,
                    S_, VD_, S_, H_);

    // 8. x2 = x + attn_out @ o_w
    gemm<false, 8>(b.ao, D_, 0, o_w, D_, 0, b.x2, D_, 0, S_, D_, D_, 1,
                   1.f, nullptr, x, D_, 0);

    // 9. h2 = rmsnorm(x2); ffn = gelu(h2 @ w1 + b1); out = x2 + ffn @ w2 + b2
    rmsnorm_k<<<S_, 256>>>(b.x2, D_, b.h2, D_, norm2_w, D_);
    gemm<false, 6>(b.h2, D_, 0, ffn_w1, DFF_, 0, b.ffn, DFF_, 0, S_, DFF_, D_, 1,
                   1.f, ffn_b1);
    gemm<false, 10>(b.ffn, DFF_, 0, ffn_w2, D_, 0, out, D_, 0, S_, D_, DFF_, 1,
                    1.f, ffn_b2, b.x2, D_, 0);

    (void)in_sizes; (void)n_in; (void)out_size;
}

// round 9
// speedup vs baseline: 2.0032x; 2.0032x over previous
#include <cuda_runtime.h>
#include <cuda_bf16.h>
#include <stdint.h>
#include <math.h>

// ---------------- problem constants ----------------
#define S_ 2048
#define D_ 2048
#define H_ 16
#define QR_ 1536
#define KVR_ 512
#define NOPE_ 128
#define RD_ 64
#define VD_ 128
#define QKD_ 192          // NOPE + RD
#define DFF_ 8192
#define HQKD_ (H_*QKD_)   // 3072
#define HKV_ (H_*(NOPE_+VD_)) // 4096

// ---------------- scratch (static device globals; allocation-free) ----------------
__device__ float g_hs [(size_t)S_*D_];
__device__ float g_qa [(size_t)S_*QR_];
__device__ float g_q  [(size_t)S_*HQKD_];
__device__ float g_kva[(size_t)S_*(KVR_+RD_)];
__device__ float g_ckv[(size_t)S_*KVR_];
__device__ float g_kv [(size_t)S_*HKV_];
__device__ float g_kpe[(size_t)S_*RD_];
__device__ float g_kf [(size_t)H_*S_*QKD_];
__device__ float g_sc [(size_t)H_*S_*S_];   // 256 MB
__device__ float g_ao [(size_t)S_*D_];
__device__ float g_x2 [(size_t)S_*D_];
__device__ float g_h2 [(size_t)S_*D_];
__device__ float g_ffn[(size_t)S_*DFF_];

// ---------------- tf32 helpers ----------------
__device__ __forceinline__ uint32_t f2tf(float f) {
    uint32_t r;
    asm("cvt.rna.tf32.f32 %0, %1;" : "=r"(r) : "f"(f));
    return r;
}

__device__ __forceinline__ void mma_tf32(float* c, const uint32_t* a, const uint32_t* b) {
    asm volatile(
        "mma.sync.aligned.m16n8k8.row.col.f32.tf32.tf32.f32 "
        "{%0,%1,%2,%3}, {%4,%5,%6,%7}, {%8,%9}, {%0,%1,%2,%3};"
        : "+f"(c[0]), "+f"(c[1]), "+f"(c[2]), "+f"(c[3])
        : "r"(a[0]), "r"(a[1]), "r"(a[2]), "r"(a[3]),
          "r"(b[0]), "r"(b[1]));
}

// ---------------- tensor-core GEMM (conflict-free smem) ----------------
// C[M,N] = A[M,K] @ op(B); A row-major (lda).
//   BT=false: B is [K,N] (ldb row stride)
//   BT=true : B is [N,K] (ldb row stride)  => C = A @ B^T
// EPI bitmask: 1=causal mask+scale, 2=+bias[n], 4=gelu(exact), 8=+aux[m,n],
//              16=causal K-limit (K_eff = m0+BM)
// Requirements: M % 128 == 0, K % 16 == 0, N % 4 == 0 (all calls satisfy).
//
// Bank derivations (stride 136 == 8 mod 32):
//   loads : bank = (8*(ks*8+c) + r) mod 32 = 8c + q + const  -> 32 distinct. CF.
//   A sts : row-per-lane mapping -> bank = 8*(kq+i) + lane + const -> 32 distinct. CF.
//   B sts (BT=false): STS.128 n-contiguous -> lanes cover all banks. CF.
#define BM 128
#define BN 128
#define BKT 16
#define LDW 136   // 136 mod 32 == 8

template<bool BT, int EPI>
__global__ void __launch_bounds__(256) tcgemm_k(
    const float* __restrict__ A, int lda, long long sA,
    const float* __restrict__ B, int ldb, long long sB,
    float* __restrict__ C, int ldc, long long sC,
    int M, int N, int K, float scale,
    const float* __restrict__ bias,
    const float* __restrict__ aux, int ldaux, long long sAux)
{
    const int bz = blockIdx.z;
    const float* Ab = A + (long long)bz * sA;
    const float* Bb = B + (long long)bz * sB;
    float* Cb = C + (long long)bz * sC;
    const float* auxb = aux ? aux + (long long)bz * sAux : nullptr;

    const int m0 = blockIdx.y * BM;
    const int n0 = blockIdx.x * BN;
    if ((EPI & 1) && n0 > m0 + BM - 1) return;   // fully-masked causal block

    int Keff = K;
    if (EPI & 16) { int kl = m0 + BM; Keff = kl < K ? kl : K; }

    __shared__ uint32_t As[2][BKT][LDW];   // [k][m], tf32 bits
    __shared__ uint32_t Bs[2][BKT][LDW];   // [k][n], tf32 bits

    const int tid = threadIdx.x;
    const int lane = tid & 31;
    const int wid = tid >> 5;
    const int wm = (wid & 1) * 64;    // warp m-offset in tile
    const int wn = (wid >> 1) * 32;   // warp n-offset in tile

    float acc[4][4][4];
    #pragma unroll
    for (int i = 0; i < 4; i++)
        #pragma unroll
        for (int j = 0; j < 4; j++)
            #pragma unroll
            for (int c = 0; c < 4; c++) acc[i][j][c] = 0.f;

    // ---- global-load staging ----
    // A (and BT=true B): one row per lane -> conflict-free scalar STS.
    const int a_row = (wid & 3) * 32 + lane;   // 0..127
    const int a_kq  = (wid >> 2) * 4;          // 0 or 4 (second chunk at +8)
    // BT=false B: row-major rows of B -> STS.128.
    const int bk_f = tid >> 5;                 // k row (0..7), +8 for second
    const int bn_f = (tid & 31) * 4;           // n offset

    float4 ag0, ag1, bg0, bg1;
    const float4 z4 = make_float4(0.f, 0.f, 0.f, 0.f);

    auto ldg = [&](int k0) {
        const float* ap = Ab + (size_t)(m0 + a_row) * lda + k0 + a_kq;
        ag0 = *(const float4*)(ap);
        ag1 = *(const float4*)(ap + 8);
        if (!BT) {
            int n = n0 + bn_f;
            bool ok = n < N;
            bg0 = ok ? *(const float4*)(Bb + (size_t)(k0 + bk_f) * ldb + n) : z4;
            bg1 = ok ? *(const float4*)(Bb + (size_t)(k0 + bk_f + 8) * ldb + n) : z4;
        } else {
            int gn = n0 + a_row;
            bool ok = gn < N;
            const float* bp = Bb + (size_t)gn * ldb + k0 + a_kq;
            bg0 = ok ? *(const float4*)(bp) : z4;
            bg1 = ok ? *(const float4*)(bp + 8) : z4;
        }
    };

    auto sts = [&](int buf) {
        As[buf][a_kq + 0][a_row] = f2tf(ag0.x);
        As[buf][a_kq + 1][a_row] = f2tf(ag0.y);
        As[buf][a_kq + 2][a_row] = f2tf(ag0.z);
        As[buf][a_kq + 3][a_row] = f2tf(ag0.w);
        As[buf][a_kq + 8][a_row] = f2tf(ag1.x);
        As[buf][a_kq + 9][a_row] = f2tf(ag1.y);
        As[buf][a_kq +10][a_row] = f2tf(ag1.z);
        As[buf][a_kq +11][a_row] = f2tf(ag1.w);
        if (!BT) {
            uint4 v0 = make_uint4(f2tf(bg0.x), f2tf(bg0.y), f2tf(bg0.z), f2tf(bg0.w));
            uint4 v1 = make_uint4(f2tf(bg1.x), f2tf(bg1.y), f2tf(bg1.z), f2tf(bg1.w));
            *(uint4*)&Bs[buf][bk_f][bn_f] = v0;
            *(uint4*)&Bs[buf][bk_f + 8][bn_f] = v1;
        } else {
            Bs[buf][a_kq + 0][a_row] = f2tf(bg0.x);
            Bs[buf][a_kq + 1][a_row] = f2tf(bg0.y);
            Bs[buf][a_kq + 2][a_row] = f2tf(bg0.z);
            Bs[buf][a_kq + 3][a_row] = f2tf(bg0.w);
            Bs[buf][a_kq + 8][a_row] = f2tf(bg1.x);
            Bs[buf][a_kq + 9][a_row] = f2tf(bg1.y);
            Bs[buf][a_kq +10][a_row] = f2tf(bg1.z);
            Bs[buf][a_kq +11][a_row] = f2tf(bg1.w);
        }
    };

    auto comp = [&](int buf) {
        #pragma unroll
        for (int ks = 0; ks < 2; ks++) {
            const int kk = ks * 8 + (lane & 3);
            uint32_t af[4][4], bf[4][2];
            #pragma unroll
            for (int mt = 0; mt < 4; mt++) {
                int r = wm + mt * 16 + (lane >> 2);
                af[mt][0] = As[buf][kk][r];
                af[mt][1] = As[buf][kk][r + 8];
                af[mt][2] = As[buf][kk + 4][r];
                af[mt][3] = As[buf][kk + 4][r + 8];
            }
            #pragma unroll
            for (int nt = 0; nt < 4; nt++) {
                int c = wn + nt * 8 + (lane >> 2);
                bf[nt][0] = Bs[buf][kk][c];
                bf[nt][1] = Bs[buf][kk + 4][c];
            }
            #pragma unroll
            for (int mt = 0; mt < 4; mt++)
                #pragma unroll
                for (int nt = 0; nt < 4; nt++)
                    mma_tf32(acc[mt][nt], af[mt], bf[nt]);
        }
    };

    const int T = Keff / BKT;
    ldg(0);
    sts(0);
    __syncthreads();
    for (int t = 0; t < T; t++) {
        int buf = t & 1;
        if (t + 1 < T) ldg((t + 1) * BKT);
        comp(buf);
        if (t + 1 < T) sts(buf ^ 1);
        __syncthreads();
    }

    // epilogue
    #pragma unroll
    for (int mt = 0; mt < 4; mt++) {
        int gm0 = m0 + wm + mt * 16 + (lane >> 2);
        #pragma unroll
        for (int nt = 0; nt < 4; nt++) {
            int gn = n0 + wn + nt * 8 + 2 * (lane & 3);
            if (gn >= N) continue;
            #pragma unroll
            for (int h = 0; h < 2; h++) {
                int gm = gm0 + h * 8;
                float v0 = acc[mt][nt][h * 2 + 0];
                float v1 = acc[mt][nt][h * 2 + 1];
                if (EPI & 1) {
                    v0 = (gn     <= gm) ? v0 * scale : -1e30f;
                    v1 = (gn + 1 <= gm) ? v1 * scale : -1e30f;
                }
                if (EPI & 2) { v0 += bias[gn]; v1 += bias[gn + 1]; }
                if (EPI & 4) {
                    v0 = 0.5f * v0 * (1.f + erff(v0 * 0.70710678118654752f));
                    v1 = 0.5f * v1 * (1.f + erff(v1 * 0.70710678118654752f));
                }
                if (EPI & 8) {
                    v0 += auxb[(long long)gm * ldaux + gn];
                    v1 += auxb[(long long)gm * ldaux + gn + 1];
                }
                *(float2*)&Cb[(long long)gm * ldc + gn] = make_float2(v0, v1);
            }
        }
    }
}

// ---------------- rmsnorm: one block per row ----------------
__global__ void rmsnorm_k(const float* __restrict__ src, int sld,
                          float* __restrict__ dst, int dld,
                          const float* __restrict__ w, int n)
{
    __shared__ float sh[8];
    __shared__ float rs_sh;
    long long r = blockIdx.x;
    const float* s = src + r * sld;
    float* d = dst + r * dld;
    int tid = threadIdx.x;

    float ss = 0.f;
    for (int i = tid; i < n; i += 256) { float v = s[i]; ss += v * v; }
    #pragma unroll
    for (int o = 16; o; o >>= 1) ss += __shfl_xor_sync(0xffffffffu, ss, o);
    if ((tid & 31) == 0) sh[tid >> 5] = ss;
    __syncthreads();
    if (tid == 0) {
        float t = 0.f;
        #pragma unroll
        for (int i = 0; i < 8; i++) t += sh[i];
        rs_sh = rsqrtf(t / (float)n + 1e-5f);
    }
    __syncthreads();
    float rs = rs_sh;
    for (int i = tid; i < n; i += 256) d[i] = s[i] * rs * w[i];
}

// ---------------- RoPE ----------------
__device__ __forceinline__ void rope_pair(int s, int j, float x0, float x1,
                                          float& o_lo, float& o_hi)
{
    float e = (float)(2 * j) / 64.f;
    float inv = 1.f / powf(10000.f, e);
    float ang = (float)s * inv;
    float sn, c;
    sincosf(ang, &sn, &c);
    o_lo = x0 * c - x1 * sn;
    o_hi = x1 * c + x0 * sn;
}

__global__ void rope_q_k(float* __restrict__ q)   // in-place on pe slice of g_q
{
    int s = blockIdx.x, h = blockIdx.y, j = threadIdx.x;  // 32 threads
    float* p = q + (long long)s * HQKD_ + h * QKD_ + NOPE_;
    float x0 = p[2 * j], x1 = p[2 * j + 1];
    __syncwarp();
    float lo, hi;
    rope_pair(s, j, x0, x1, lo, hi);
    p[j] = lo;
    p[32 + j] = hi;
}

__global__ void rope_kpe_k(const float* __restrict__ kva, float* __restrict__ kpe)
{
    int s = blockIdx.x, j = threadIdx.x;
    const float* p = kva + (long long)s * (KVR_ + RD_) + KVR_;
    float lo, hi;
    rope_pair(s, j, p[2 * j], p[2 * j + 1], lo, hi);
    kpe[(long long)s * RD_ + j] = lo;
    kpe[(long long)s * RD_ + 32 + j] = hi;
}

// ---------------- pack k_full = [k_nope | roped k_pe] per head ----------------
__global__ void pack_kf_k(const float* __restrict__ kv,
                          const float* __restrict__ kpe,
                          float* __restrict__ kf)
{
    int s = blockIdx.x, h = blockIdx.y, c = threadIdx.x;  // 192 threads
    float v = (c < NOPE_) ? kv[(long long)s * HKV_ + h * (NOPE_ + VD_) + c]
                          : kpe[(long long)s * RD_ + (c - NOPE_)];
    kf[((long long)h * S_ + s) * QKD_ + c] = v;
}

// ---------------- causal softmax (zero tail only up to 128-block boundary) ----
__global__ void softmax_k(float* __restrict__ sc)
{
    __shared__ float sh[8];
    __shared__ float bval;
    int q = blockIdx.x, h = blockIdx.y;
    float* row = sc + ((long long)h * S_ + q) * (long long)S_;
    int n = q + 1;
    int tid = threadIdx.x;

    float mx = -1e30f;
    for (int i = tid; i < n; i += 256) mx = fmaxf(mx, row[i]);
    #pragma unroll
    for (int o = 16; o; o >>= 1) mx = fmaxf(mx, __shfl_xor_sync(0xffffffffu, mx, o));
    if ((tid & 31) == 0) sh[tid >> 5] = mx;
    __syncthreads();
    if (tid == 0) {
        float m = sh[0];
        #pragma unroll
        for (int i = 1; i < 8; i++) m = fmaxf(m, sh[i]);
        bval = m;
    }
    __syncthreads();
    float M = bval;
    __syncthreads();

    float sum = 0.f;
    for (int i = tid; i < n; i += 256) {
        float e = expf(row[i] - M);
        row[i] = e;
        sum += e;
    }
    #pragma unroll
    for (int o = 16; o; o >>= 1) sum += __shfl_xor_sync(0xffffffffu, sum, o);
    if ((tid & 31) == 0) sh[tid >> 5] = sum;
    __syncthreads();
    if (tid == 0) {
        float t = 0.f;
        #pragma unroll
        for (int i = 0; i < 8; i++) t += sh[i];
        bval = 1.f / t;
    }
    __syncthreads();
    float inv = bval;
    for (int i = tid; i < n; i += 256) row[i] *= inv;
    // PV GEMM only reads K up to this row's 128-block end — zero just that tail.
    int zend = ((q >> 7) + 1) << 7;
    for (int i = n + tid; i < zend; i += 256) row[i] = 0.f;
}

// ---------------- host side ----------------
struct Bufs {
    float *hs, *qa, *q, *kva, *ckv, *kv, *kpe, *kf, *sc, *ao, *x2, *h2, *ffn;
};

static Bufs get_bufs()
{
    static Bufs b = [] {
        Bufs t;
        cudaGetSymbolAddress((void**)&t.hs,  g_hs);
        cudaGetSymbolAddress((void**)&t.qa,  g_qa);
        cudaGetSymbolAddress((void**)&t.q,   g_q);
        cudaGetSymbolAddress((void**)&t.kva, g_kva);
        cudaGetSymbolAddress((void**)&t.ckv, g_ckv);
        cudaGetSymbolAddress((void**)&t.kv,  g_kv);
        cudaGetSymbolAddress((void**)&t.kpe, g_kpe);
        cudaGetSymbolAddress((void**)&t.kf,  g_kf);
        cudaGetSymbolAddress((void**)&t.sc,  g_sc);
        cudaGetSymbolAddress((void**)&t.ao,  g_ao);
        cudaGetSymbolAddress((void**)&t.x2,  g_x2);
        cudaGetSymbolAddress((void**)&t.h2,  g_h2);
        cudaGetSymbolAddress((void**)&t.ffn, g_ffn);
        return t;
    }();
    return b;
}

template<bool BT, int EPI>
static void gemm(const float* A, int lda, long long sA,
                 const float* B, int ldb, long long sB,
                 float* C, int ldc, long long sC,
                 int M, int N, int K, int batch,
                 float scale = 1.f,
                 const float* bias = nullptr,
                 const float* aux = nullptr, int ldaux = 0, long long sAux = 0)
{
    dim3 grid((N + BN - 1) / BN, (M + BM - 1) / BM, batch);
    tcgemm_k<BT, EPI><<<grid, 256>>>(A, lda, sA, B, ldb, sB, C, ldc, sC,
                                     M, N, K, scale, bias, aux, ldaux, sAux);
}

extern "C" void kernel_launch(void* const* d_in, const int* in_sizes, int n_in,
                              void* d_out, int out_size)
{
    const float* x        = (const float*)d_in[0];
    const float* norm1_w  = (const float*)d_in[1];
    const float* q_a_w    = (const float*)d_in[2];
    const float* q_a_ln_w = (const float*)d_in[3];
    const float* q_b_w    = (const float*)d_in[4];
    const float* kv_a_w   = (const float*)d_in[5];
    const float* kv_a_ln_w= (const float*)d_in[6];
    const float* kv_b_w   = (const float*)d_in[7];
    const float* o_w      = (const float*)d_in[8];
    const float* norm2_w  = (const float*)d_in[9];
    const float* ffn_w1   = (const float*)d_in[10];
    const float* ffn_b1   = (const float*)d_in[11];
    const float* ffn_w2   = (const float*)d_in[12];
    const float* ffn_b2   = (const float*)d_in[13];
    float* out = (float*)d_out;

    Bufs b = get_bufs();

    // 1. hs = rmsnorm(x) * norm1_w   (B=1 so layout is (S, D))
    rmsnorm_k<<<S_, 256>>>(x, D_, b.hs, D_, norm1_w, D_);

    // 2. q_a = hs @ q_a_w ; rmsnorm ; q = @ q_b_w
    gemm<false, 0>(b.hs, D_, 0, q_a_w, QR_, 0, b.qa, QR_, 0, S_, QR_, D_, 1);
    rmsnorm_k<<<S_, 256>>>(b.qa, QR_, b.qa, QR_, q_a_ln_w, QR_);
    gemm<false, 0>(b.qa, QR_, 0, q_b_w, HQKD_, 0, b.q, HQKD_, 0, S_, HQKD_, QR_, 1);

    // 3. kv_a = hs @ kv_a_w ; split ; rmsnorm ; kv = @ kv_b_w
    gemm<false, 0>(b.hs, D_, 0, kv_a_w, KVR_ + RD_, 0, b.kva, KVR_ + RD_, 0,
                   S_, KVR_ + RD_, D_, 1);
    rmsnorm_k<<<S_, 256>>>(b.kva, KVR_ + RD_, b.ckv, KVR_, kv_a_ln_w, KVR_);
    gemm<false, 0>(b.ckv, KVR_, 0, kv_b_w, HKV_, 0, b.kv, HKV_, 0, S_, HKV_, KVR_, 1);

    // 4. RoPE + pack k_full
    rope_q_k<<<dim3(S_, H_), 32>>>(b.q);
    rope_kpe_k<<<S_, 32>>>(b.kva, b.kpe);
    pack_kf_k<<<dim3(S_, H_), 192>>>(b.kv, b.kpe, b.kf);

    // 5. scores = (q_full @ k_full^T) * 1/sqrt(192), causal (upper blocks skipped)
    const float scale = 0.072168783648703216f; // 1/sqrt(192)
    gemm<true, 1>(b.q, HQKD_, (long long)QKD_,
                  b.kf, QKD_, (long long)S_ * QKD_,
                  b.sc, S_, (long long)S_ * S_,
                  S_, S_, QKD_, H_, scale);

    // 6. causal softmax (zeros tail to the 128-block boundary)
    softmax_k<<<dim3(S_, H_), 256>>>(b.sc);

    // 7. attn_out = P @ V  (V strided in kv; causal K-limit: K_eff = m0+128)
    gemm<false, 16>(b.sc, S_, (long long)S_ * S_,
                    b.kv + NOPE_, HKV_, (long long)(NOPE_ + VD_),
                    b.ao, D_, (long long)VD_,
                    S_, VD_, S_, H_);

    // 8. x2 = x + attn_out @ o_w
    gemm<false, 8>(b.ao, D_, 0, o_w, D_, 0, b.x2, D_, 0, S_, D_, D_, 1,
                   1.f, nullptr, x, D_, 0);

    // 9. h2 = rmsnorm(x2); ffn = gelu(h2 @ w1 + b1); out = x2 + ffn @ w2 + b2
    rmsnorm_k<<<S_, 256>>>(b.x2, D_, b.h2, D_, norm2_w, D_);
    gemm<false, 6>(b.h2, D_, 0, ffn_w1, DFF_, 0, b.ffn, DFF_, 0, S_, DFF_, D_, 1,
                   1.f, ffn_b1);
    gemm<false, 10>(b.ffn, DFF_, 0, ffn_w2, D_, 0, out, D_, 0, S_, D_, DFF_, 1,
                    1.f, ffn_b2, b.x2, D_, 0);

    (void)in_sizes; (void)n_in; (void)out_size;
}

// round 12
// speedup vs baseline: 2.7446x; 1.3701x over previous
#include <cuda_runtime.h>
#include <cuda_bf16.h>
#include <stdint.h>
#include <math.h>

// ---------------- problem constants ----------------
#define S_ 2048
#define D_ 2048
#define H_ 16
#define QR_ 1536
#define KVR_ 512
#define NOPE_ 128
#define RD_ 64
#define VD_ 128
#define QKD_ 192          // NOPE + RD
#define DFF_ 8192
#define HQKD_ (H_*QKD_)   // 3072
#define HKV_ (H_*(NOPE_+VD_)) // 4096

// ---------------- scratch (static device globals; allocation-free) ----------------
__device__ float g_hs [(size_t)S_*D_];
__device__ float g_qa [(size_t)S_*QR_];
__device__ float g_q  [(size_t)S_*HQKD_];
__device__ float g_kva[(size_t)S_*(KVR_+RD_)];
__device__ float g_ckv[(size_t)S_*KVR_];
__device__ float g_kv [(size_t)S_*HKV_];
__device__ float g_kpe[(size_t)S_*RD_];
__device__ float g_kf [(size_t)H_*S_*QKD_];
__device__ float g_sc [(size_t)H_*S_*S_];   // 256 MB
__device__ float g_ao [(size_t)S_*D_];
__device__ float g_x2 [(size_t)S_*D_];
__device__ float g_h2 [(size_t)S_*D_];
__device__ float g_ffn[(size_t)S_*DFF_];

// ---------------- tf32 helpers ----------------
__device__ __forceinline__ uint32_t f2tf(float f) {
    uint32_t r;
    asm("cvt.rna.tf32.f32 %0, %1;" : "=r"(r) : "f"(f));
    return r;
}

__device__ __forceinline__ void mma_tf32(float* c, const uint32_t* a, const uint32_t* b) {
    asm volatile(
        "mma.sync.aligned.m16n8k8.row.col.f32.tf32.tf32.f32 "
        "{%0,%1,%2,%3}, {%4,%5,%6,%7}, {%8,%9}, {%0,%1,%2,%3};"
        : "+f"(c[0]), "+f"(c[1]), "+f"(c[2]), "+f"(c[3])
        : "r"(a[0]), "r"(a[1]), "r"(a[2]), "r"(a[3]),
          "r"(b[0]), "r"(b[1]));
}

// ---------------- tensor-core GEMM (fp32 smem, CF-derived layouts) ----------------
// C[M,N] = A[M,K] @ op(B); A row-major (lda).
//   BT=false: B is [K,N] (ldb row stride)
//   BT=true : B is [N,K] (ldb row stride)  => C = A @ B^T
// EPI bitmask: 1=causal mask+scale, 2=+bias[n], 4=gelu(exact), 8=+aux[m,n],
//              16=causal K-limit (K_eff = m0+BM)
// Requirements: M % 128 == 0, K % 16 == 0, N % 4 == 0 (all calls satisfy).
//
// smem (fp32):
//   A  [buf][128][20] : frag loads bank = 20*(16a+q)+kk = 20q+c (+consts) -> 32 distinct, CF.
//                       stores: STS.128 @ ar*20+ak -> 1 extra phase per quarter-warp (~1.25x).
//   Bf [buf][16][136] : frag loads bank = 8c+q (+consts) -> CF. stores STS.128 n-contig -> CF.
//   Bt [buf][128][20] : same derivations as A.
#define BM 128
#define BN 128
#define BKT 16

template<bool BT, int EPI>
__global__ void __launch_bounds__(256) tcgemm_k(
    const float* __restrict__ A, int lda, long long sA,
    const float* __restrict__ B, int ldb, long long sB,
    float* __restrict__ C, int ldc, long long sC,
    int M, int N, int K, float scale,
    const float* __restrict__ bias,
    const float* __restrict__ aux, int ldaux, long long sAux)
{
    const int bz = blockIdx.z;
    const float* Ab = A + (long long)bz * sA;
    const float* Bb = B + (long long)bz * sB;
    float* Cb = C + (long long)bz * sC;
    const float* auxb = aux ? aux + (long long)bz * sAux : nullptr;

    const int m0 = blockIdx.y * BM;
    const int n0 = blockIdx.x * BN;
    if ((EPI & 1) && n0 > m0 + BM - 1) return;   // fully-masked causal block

    int Keff = K;
    if (EPI & 16) { int kl = m0 + BM; Keff = kl < K ? kl : K; }

    // pool: A = [0, 5120) floats (2 bufs x 128x20)
    //       B = [5120, 10240): BT=false uses 2 x 16x136 = 4352; BT=true 2 x 128x20 = 5120
    __shared__ __align__(16) float pool[10240];   // 40 KB static
    float* Apool = pool;
    float* Bpool = pool + 5120;

    const int tid = threadIdx.x;
    const int lane = tid & 31;
    const int wid = tid >> 5;
    const int wm = (wid & 1) * 64;    // warp m-offset in tile
    const int wn = (wid >> 1) * 32;   // warp n-offset in tile

    float acc[4][4][4];
    #pragma unroll
    for (int i = 0; i < 4; i++)
        #pragma unroll
        for (int j = 0; j < 4; j++)
            #pragma unroll
            for (int c = 0; c < 4; c++) acc[i][j][c] = 0.f;

    // ---- global-load staging (proven coalesced R4 geometry) ----
    const int ar = tid >> 2;           // A row within tile (0..63), +64 for second
    const int ak = (tid & 3) * 4;      // A k-offset (0,4,8,12)
    const int bk_f = tid >> 5;         // BT=false: k row (0..7), +8 for second
    const int bn_f = (tid & 31) * 4;   // BT=false: n offset

    float4 ag0, ag1, bg0, bg1;
    const float4 z4 = make_float4(0.f, 0.f, 0.f, 0.f);

    auto ldg = [&](int k0) {
        ag0 = *(const float4*)(Ab + (size_t)(m0 + ar) * lda + k0 + ak);
        ag1 = *(const float4*)(Ab + (size_t)(m0 + ar + 64) * lda + k0 + ak);
        if (!BT) {
            int n = n0 + bn_f;
            bool ok = n < N;
            bg0 = ok ? *(const float4*)(Bb + (size_t)(k0 + bk_f) * ldb + n) : z4;
            bg1 = ok ? *(const float4*)(Bb + (size_t)(k0 + bk_f + 8) * ldb + n) : z4;
        } else {
            int n1 = n0 + ar, n2 = n1 + 64;
            bg0 = (n1 < N) ? *(const float4*)(Bb + (size_t)n1 * ldb + k0 + ak) : z4;
            bg1 = (n2 < N) ? *(const float4*)(Bb + (size_t)n2 * ldb + k0 + ak) : z4;
        }
    };

    auto sts = [&](int buf) {
        float* As = Apool + buf * 2560;
        *(float4*)&As[ar * 20 + ak] = ag0;
        *(float4*)&As[(ar + 64) * 20 + ak] = ag1;
        if (!BT) {
            float* Bf = Bpool + buf * 2176;
            *(float4*)&Bf[bk_f * 136 + bn_f] = bg0;
            *(float4*)&Bf[(bk_f + 8) * 136 + bn_f] = bg1;
        } else {
            float* Bt = Bpool + buf * 2560;
            *(float4*)&Bt[ar * 20 + ak] = bg0;
            *(float4*)&Bt[(ar + 64) * 20 + ak] = bg1;
        }
    };

    auto comp = [&](int buf) {
        const float* As = Apool + buf * 2560;
        const float* Bf = Bpool + buf * 2176;
        const float* Bt = Bpool + buf * 2560;
        #pragma unroll
        for (int ks = 0; ks < 2; ks++) {
            const int kk = ks * 8 + (lane & 3);
            uint32_t af[4][4], bf[4][2];
            #pragma unroll
            for (int mt = 0; mt < 4; mt++) {
                int r = wm + mt * 16 + (lane >> 2);
                af[mt][0] = f2tf(As[r * 20 + kk]);
                af[mt][1] = f2tf(As[(r + 8) * 20 + kk]);
                af[mt][2] = f2tf(As[r * 20 + kk + 4]);
                af[mt][3] = f2tf(As[(r + 8) * 20 + kk + 4]);
            }
            #pragma unroll
            for (int nt = 0; nt < 4; nt++) {
                int c = wn + nt * 8 + (lane >> 2);
                if (!BT) {
                    bf[nt][0] = f2tf(Bf[kk * 136 + c]);
                    bf[nt][1] = f2tf(Bf[(kk + 4) * 136 + c]);
                } else {
                    bf[nt][0] = f2tf(Bt[c * 20 + kk]);
                    bf[nt][1] = f2tf(Bt[c * 20 + kk + 4]);
                }
            }
            #pragma unroll
            for (int mt = 0; mt < 4; mt++)
                #pragma unroll
                for (int nt = 0; nt < 4; nt++)
                    mma_tf32(acc[mt][nt], af[mt], bf[nt]);
        }
    };

    const int T = Keff / BKT;
    ldg(0);
    sts(0);
    __syncthreads();
    for (int t = 0; t < T; t++) {
        int buf = t & 1;
        if (t + 1 < T) ldg((t + 1) * BKT);
        comp(buf);
        if (t + 1 < T) sts(buf ^ 1);
        __syncthreads();
    }

    // epilogue
    #pragma unroll
    for (int mt = 0; mt < 4; mt++) {
        int gm0 = m0 + wm + mt * 16 + (lane >> 2);
        #pragma unroll
        for (int nt = 0; nt < 4; nt++) {
            int gn = n0 + wn + nt * 8 + 2 * (lane & 3);
            if (gn >= N) continue;
            #pragma unroll
            for (int h = 0; h < 2; h++) {
                int gm = gm0 + h * 8;
                float v0 = acc[mt][nt][h * 2 + 0];
                float v1 = acc[mt][nt][h * 2 + 1];
                if (EPI & 1) {
                    v0 = (gn     <= gm) ? v0 * scale : -1e30f;
                    v1 = (gn + 1 <= gm) ? v1 * scale : -1e30f;
                }
                if (EPI & 2) { v0 += bias[gn]; v1 += bias[gn + 1]; }
                if (EPI & 4) {
                    v0 = 0.5f * v0 * (1.f + erff(v0 * 0.70710678118654752f));
                    v1 = 0.5f * v1 * (1.f + erff(v1 * 0.70710678118654752f));
                }
                if (EPI & 8) {
                    v0 += auxb[(long long)gm * ldaux + gn];
                    v1 += auxb[(long long)gm * ldaux + gn + 1];
                }
                *(float2*)&Cb[(long long)gm * ldc + gn] = make_float2(v0, v1);
            }
        }
    }
}

// ---------------- rmsnorm: one block per row ----------------
__global__ void rmsnorm_k(const float* __restrict__ src, int sld,
                          float* __restrict__ dst, int dld,
                          const float* __restrict__ w, int n)
{
    __shared__ float sh[8];
    __shared__ float rs_sh;
    long long r = blockIdx.x;
    const float* s = src + r * sld;
    float* d = dst + r * dld;
    int tid = threadIdx.x;

    float ss = 0.f;
    for (int i = tid; i < n; i += 256) { float v = s[i]; ss += v * v; }
    #pragma unroll
    for (int o = 16; o; o >>= 1) ss += __shfl_xor_sync(0xffffffffu, ss, o);
    if ((tid & 31) == 0) sh[tid >> 5] = ss;
    __syncthreads();
    if (tid == 0) {
        float t = 0.f;
        #pragma unroll
        for (int i = 0; i < 8; i++) t += sh[i];
        rs_sh = rsqrtf(t / (float)n + 1e-5f);
    }
    __syncthreads();
    float rs = rs_sh;
    for (int i = tid; i < n; i += 256) d[i] = s[i] * rs * w[i];
}

// ---------------- RoPE ----------------
__device__ __forceinline__ void rope_pair(int s, int j, float x0, float x1,
                                          float& o_lo, float& o_hi)
{
    float e = (float)(2 * j) / 64.f;
    float inv = 1.f / powf(10000.f, e);
    float ang = (float)s * inv;
    float sn, c;
    sincosf(ang, &sn, &c);
    o_lo = x0 * c - x1 * sn;
    o_hi = x1 * c + x0 * sn;
}

__global__ void rope_q_k(float* __restrict__ q)   // in-place on pe slice of g_q
{
    int s = blockIdx.x, h = blockIdx.y, j = threadIdx.x;  // 32 threads
    float* p = q + (long long)s * HQKD_ + h * QKD_ + NOPE_;
    float x0 = p[2 * j], x1 = p[2 * j + 1];
    __syncwarp();
    float lo, hi;
    rope_pair(s, j, x0, x1, lo, hi);
    p[j] = lo;
    p[32 + j] = hi;
}

__global__ void rope_kpe_k(const float* __restrict__ kva, float* __restrict__ kpe)
{
    int s = blockIdx.x, j = threadIdx.x;
    const float* p = kva + (long long)s * (KVR_ + RD_) + KVR_;
    float lo, hi;
    rope_pair(s, j, p[2 * j], p[2 * j + 1], lo, hi);
    kpe[(long long)s * RD_ + j] = lo;
    kpe[(long long)s * RD_ + 32 + j] = hi;
}

// ---------------- pack k_full = [k_nope | roped k_pe] per head ----------------
__global__ void pack_kf_k(const float* __restrict__ kv,
                          const float* __restrict__ kpe,
                          float* __restrict__ kf)
{
    int s = blockIdx.x, h = blockIdx.y, c = threadIdx.x;  // 192 threads
    float v = (c < NOPE_) ? kv[(long long)s * HKV_ + h * (NOPE_ + VD_) + c]
                          : kpe[(long long)s * RD_ + (c - NOPE_)];
    kf[((long long)h * S_ + s) * QKD_ + c] = v;
}

// ---------------- causal softmax (zero tail only up to 128-block boundary) ----
__global__ void softmax_k(float* __restrict__ sc)
{
    __shared__ float sh[8];
    __shared__ float bval;
    int q = blockIdx.x, h = blockIdx.y;
    float* row = sc + ((long long)h * S_ + q) * (long long)S_;
    int n = q + 1;
    int tid = threadIdx.x;

    float mx = -1e30f;
    for (int i = tid; i < n; i += 256) mx = fmaxf(mx, row[i]);
    #pragma unroll
    for (int o = 16; o; o >>= 1) mx = fmaxf(mx, __shfl_xor_sync(0xffffffffu, mx, o));
    if ((tid & 31) == 0) sh[tid >> 5] = mx;
    __syncthreads();
    if (tid == 0) {
        float m = sh[0];
        #pragma unroll
        for (int i = 1; i < 8; i++) m = fmaxf(m, sh[i]);
        bval = m;
    }
    __syncthreads();
    float M = bval;
    __syncthreads();

    float sum = 0.f;
    for (int i = tid; i < n; i += 256) {
        float e = expf(row[i] - M);
        row[i] = e;
        sum += e;
    }
    #pragma unroll
    for (int o = 16; o; o >>= 1) sum += __shfl_xor_sync(0xffffffffu, sum, o);
    if ((tid & 31) == 0) sh[tid >> 5] = sum;
    __syncthreads();
    if (tid == 0) {
        float t = 0.f;
        #pragma unroll
        for (int i = 0; i < 8; i++) t += sh[i];
        bval = 1.f / t;
    }
    __syncthreads();
    float inv = bval;
    for (int i = tid; i < n; i += 256) row[i] *= inv;
    // PV GEMM only reads K up to this row's 128-block end — zero just that tail.
    int zend = ((q >> 7) + 1) << 7;
    for (int i = n + tid; i < zend; i += 256) row[i] = 0.f;
}

// ---------------- host side ----------------
struct Bufs {
    float *hs, *qa, *q, *kva, *ckv, *kv, *kpe, *kf, *sc, *ao, *x2, *h2, *ffn;
};

static Bufs get_bufs()
{
    static Bufs b = [] {
        Bufs t;
        cudaGetSymbolAddress((void**)&t.hs,  g_hs);
        cudaGetSymbolAddress((void**)&t.qa,  g_qa);
        cudaGetSymbolAddress((void**)&t.q,   g_q);
        cudaGetSymbolAddress((void**)&t.kva, g_kva);
        cudaGetSymbolAddress((void**)&t.ckv, g_ckv);
        cudaGetSymbolAddress((void**)&t.kv,  g_kv);
        cudaGetSymbolAddress((void**)&t.kpe, g_kpe);
        cudaGetSymbolAddress((void**)&t.kf,  g_kf);
        cudaGetSymbolAddress((void**)&t.sc,  g_sc);
        cudaGetSymbolAddress((void**)&t.ao,  g_ao);
        cudaGetSymbolAddress((void**)&t.x2,  g_x2);
        cudaGetSymbolAddress((void**)&t.h2,  g_h2);
        cudaGetSymbolAddress((void**)&t.ffn, g_ffn);
        return t;
    }();
    return b;
}

template<bool BT, int EPI>
static void gemm(const float* A, int lda, long long sA,
                 const float* B, int ldb, long long sB,
                 float* C, int ldc, long long sC,
                 int M, int N, int K, int batch,
                 float scale = 1.f,
                 const float* bias = nullptr,
                 const float* aux = nullptr, int ldaux = 0, long long sAux = 0)
{
    dim3 grid((N + BN - 1) / BN, (M + BM - 1) / BM, batch);
    tcgemm_k<BT, EPI><<<grid, 256>>>(A, lda, sA, B, ldb, sB, C, ldc, sC,
                                     M, N, K, scale, bias, aux, ldaux, sAux);
}

extern "C" void kernel_launch(void* const* d_in, const int* in_sizes, int n_in,
                              void* d_out, int out_size)
{
    const float* x        = (const float*)d_in[0];
    const float* norm1_w  = (const float*)d_in[1];
    const float* q_a_w    = (const float*)d_in[2];
    const float* q_a_ln_w = (const float*)d_in[3];
    const float* q_b_w    = (const float*)d_in[4];
    const float* kv_a_w   = (const float*)d_in[5];
    const float* kv_a_ln_w= (const float*)d_in[6];
    const float* kv_b_w   = (const float*)d_in[7];
    const float* o_w      = (const float*)d_in[8];
    const float* norm2_w  = (const float*)d_in[9];
    const float* ffn_w1   = (const float*)d_in[10];
    const float* ffn_b1   = (const float*)d_in[11];
    const float* ffn_w2   = (const float*)d_in[12];
    const float* ffn_b2   = (const float*)d_in[13];
    float* out = (float*)d_out;

    Bufs b = get_bufs();

    // 1. hs = rmsnorm(x) * norm1_w   (B=1 so layout is (S, D))
    rmsnorm_k<<<S_, 256>>>(x, D_, b.hs, D_, norm1_w, D_);

    // 2. q_a = hs @ q_a_w ; rmsnorm ; q = @ q_b_w
    gemm<false, 0>(b.hs, D_, 0, q_a_w, QR_, 0, b.qa, QR_, 0, S_, QR_, D_, 1);
    rmsnorm_k<<<S_, 256>>>(b.qa, QR_, b.qa, QR_, q_a_ln_w, QR_);
    gemm<false, 0>(b.qa, QR_, 0, q_b_w, HQKD_, 0, b.q, HQKD_, 0, S_, HQKD_, QR_, 1);

    // 3. kv_a = hs @ kv_a_w ; split ; rmsnorm ; kv = @ kv_b_w
    gemm<false, 0>(b.hs, D_, 0, kv_a_w, KVR_ + RD_, 0, b.kva, KVR_ + RD_, 0,
                   S_, KVR_ + RD_, D_, 1);
    rmsnorm_k<<<S_, 256>>>(b.kva, KVR_ + RD_, b.ckv, KVR_, kv_a_ln_w, KVR_);
    gemm<false, 0>(b.ckv, KVR_, 0, kv_b_w, HKV_, 0, b.kv, HKV_, 0, S_, HKV_, KVR_, 1);

    // 4. RoPE + pack k_full
    rope_q_k<<<dim3(S_, H_), 32>>>(b.q);
    rope_kpe_k<<<S_, 32>>>(b.kva, b.kpe);
    pack_kf_k<<<dim3(S_, H_), 192>>>(b.kv, b.kpe, b.kf);

    // 5. scores = (q_full @ k_full^T) * 1/sqrt(192), causal (upper blocks skipped)
    const float scale = 0.072168783648703216f; // 1/sqrt(192)
    gemm<true, 1>(b.q, HQKD_, (long long)QKD_,
                  b.kf, QKD_, (long long)S_ * QKD_,
                  b.sc, S_, (long long)S_ * S_,
                  S_, S_, QKD_, H_, scale);

    // 6. causal softmax (zeros tail to the 128-block boundary)
    softmax_k<<<dim3(S_, H_), 256>>>(b.sc);

    // 7. attn_out = P @ V  (V strided in kv; causal K-limit: K_eff = m0+128)
    gemm<false, 16>(b.sc, S_, (long long)S_ * S_,
                    b.kv + NOPE_, HKV_, (long long)(NOPE_ + VD_),
                    b.ao, D_, (long long)VD_,
                    S_, VD_, S_, H_);

    // 8. x2 = x + attn_out @ o_w
    gemm<false, 8>(b.ao, D_, 0, o_w, D_, 0, b.x2, D_, 0, S_, D_, D_, 1,
                   1.f, nullptr, x, D_, 0);

    // 9. h2 = rmsnorm(x2); ffn = gelu(h2 @ w1 + b1); out = x2 + ffn @ w2 + b2
    rmsnorm_k<<<S_, 256>>>(b.x2, D_, b.h2, D_, norm2_w, D_);
    gemm<false, 6>(b.h2, D_, 0, ffn_w1, DFF_, 0, b.ffn, DFF_, 0, S_, DFF_, D_, 1,
                   1.f, ffn_b1);
    gemm<false, 10>(b.ffn, DFF_, 0, ffn_w2, D_, 0, out, D_, 0, S_, D_, DFF_, 1,
                    1.f, ffn_b2, b.x2, D_, 0);

    (void)in_sizes; (void)n_in; (void)out_size;
}